// round 1
// baseline (speedup 1.0000x reference)
#include <cuda_runtime.h>
#include <math.h>

#define NB 2
#define NH 64
#define NW 64
#define NC 256
#define NQ 4096
#define NK 49
#define NLEV 4

// Pyramid scratch (cascaded, un-normalized) + normalized features per level.
__device__ float g_pyr1[NB*32*32*NC];
__device__ float g_pyr2[NB*16*16*NC];
__device__ float g_pyr3[NB*8*8*NC];
__device__ float g_f2n0[NB*64*64*NC];
__device__ float g_f2n1[NB*32*32*NC];
__device__ float g_f2n2[NB*16*16*NC];
__device__ float g_f2n3[NB*8*8*NC];

// jax.image.resize(method='bilinear', antialias=True) 2x downsample taps.
// For output i over input size n: sample center c = 2i + 0.5, triangle kernel
// scaled by 2, support j in [2i-1, 2i+2], weights renormalized over valid taps.
__device__ __forceinline__ void resize_taps(int i, int n, int jj[4], float ww[4]) {
    float c = 2.0f * (float)i + 0.5f;
    float s = 0.0f;
#pragma unroll
    for (int t = 0; t < 4; t++) {
        int j = 2 * i - 1 + t;
        float w = 0.0f;
        if (j >= 0 && j < n) w = 1.0f - 0.5f * fabsf(c - (float)j);
        jj[t] = j < 0 ? 0 : (j > n - 1 ? n - 1 : j);
        ww[t] = w;
        s += w;
    }
    float inv = 1.0f / s;
#pragma unroll
    for (int t = 0; t < 4; t++) ww[t] *= inv;
}

__global__ void downsample_kernel(const float* __restrict__ in, float* __restrict__ out,
                                  int Hi, int Wi) {
    int Ho = Hi >> 1, Wo = Wi >> 1;
    int p = blockIdx.x;
    int b = blockIdx.y;
    int yo = p / Wo, xo = p % Wo;
    int c = threadIdx.x;
    int jy[4], jx[4];
    float wy[4], wx[4];
    resize_taps(yo, Hi, jy, wy);
    resize_taps(xo, Wi, jx, wx);
    const float* ib = in + (size_t)b * Hi * Wi * NC;
    float acc = 0.0f;
#pragma unroll
    for (int a = 0; a < 4; a++) {
        float r = 0.0f;
#pragma unroll
        for (int t = 0; t < 4; t++)
            r += wx[t] * ib[((size_t)jy[a] * Wi + jx[t]) * NC + c];
        acc += wy[a] * r;
    }
    out[(((size_t)b * Ho + yo) * Wo + xo) * NC + c] = acc;
}

// Per-pixel L2 normalize over C=256 (one block per pixel, 256 threads).
__global__ void normalize_kernel(const float* __restrict__ in, float* __restrict__ out, int HW) {
    int p = blockIdx.x, b = blockIdx.y;
    size_t off = ((size_t)b * HW + p) * NC + threadIdx.x;
    float x = in[off];
    __shared__ float red[8];
    __shared__ float sc;
    float s = x * x;
#pragma unroll
    for (int o = 16; o > 0; o >>= 1) s += __shfl_xor_sync(0xffffffffu, s, o);
    if ((threadIdx.x & 31) == 0) red[threadIdx.x >> 5] = s;
    __syncthreads();
    if (threadIdx.x == 0) {
        float t = 0.0f;
#pragma unroll
        for (int i = 0; i < 8; i++) t += red[i];
        sc = 1.0f / (sqrtf(t) + 1e-6f);
    }
    __syncthreads();
    out[off] = x * sc;
}

// Main kernel: one block per (b, n) query. 256 threads.
// Stage A: feat1 = normalize(bilinear(fmap1, coords1)) into smem.
// Stage B (per level): D[8][8] = dot(feat1, f2n[window]) via warp-per-position
//                      reductions; then 49 outputs from scalar bilinear weights.
__global__ void __launch_bounds__(256) corr_kernel(
    const float* __restrict__ fmap1,
    const float* __restrict__ coords1,
    const float* __restrict__ coords2,
    const float* __restrict__ f2n0,
    const float* __restrict__ f2n1,
    const float* __restrict__ f2n2,
    const float* __restrict__ f2n3,
    float* __restrict__ out) {
    int b = blockIdx.y;
    int n = blockIdx.x;
    int tid = threadIdx.x;
    int lane = tid & 31, wid = tid >> 5;

    __shared__ float feat1[NC];
    __shared__ float D[64];
    __shared__ float red[8];
    __shared__ float sscale;

    // ---- Stage A: feat1 ----
    float cx = coords1[((size_t)b * NQ + n) * 2 + 0];
    float cy = coords1[((size_t)b * NQ + n) * 2 + 1];
    int fx0 = (int)floorf(cx);
    int fy0 = (int)floorf(cy);
    int x0 = min(max(fx0, 0), NW - 1);
    int x1 = min(max(fx0 + 1, 0), NW - 1);
    int y0 = min(max(fy0, 0), NH - 1);
    int y1 = min(max(fy0 + 1, 0), NH - 1);
    float x0f = (float)x0, x1f = (float)x1, y0f = (float)y0, y1f = (float)y1;
    float wa = (x1f - cx) * (y1f - cy);
    float wb = (x1f - cx) * (cy - y0f);
    float wc = (cx - x0f) * (y1f - cy);
    float wd = (cx - x0f) * (cy - y0f);
    const float* fb1 = fmap1 + (size_t)b * NH * NW * NC;
    float v = wa * fb1[((size_t)y0 * NW + x0) * NC + tid] +
              wb * fb1[((size_t)y1 * NW + x0) * NC + tid] +
              wc * fb1[((size_t)y0 * NW + x1) * NC + tid] +
              wd * fb1[((size_t)y1 * NW + x1) * NC + tid];
    float s = v * v;
#pragma unroll
    for (int o = 16; o > 0; o >>= 1) s += __shfl_xor_sync(0xffffffffu, s, o);
    if (lane == 0) red[wid] = s;
    __syncthreads();
    if (tid == 0) {
        float t = 0.0f;
#pragma unroll
        for (int i = 0; i < 8; i++) t += red[i];
        sscale = 1.0f / (sqrtf(t) + 1e-6f);
    }
    __syncthreads();
    feat1[tid] = v * sscale;
    __syncthreads();

    float qx = coords2[((size_t)b * NQ + n) * 2 + 0];
    float qy = coords2[((size_t)b * NQ + n) * 2 + 1];

    const float* levels[NLEV] = {f2n0, f2n1, f2n2, f2n3};

#pragma unroll
    for (int l = 0; l < NLEV; l++) {
        const int Hl = NH >> l, Wl = NW >> l;
        const float* f2n = levels[l];
        const float scl = (float)(1 << l);
        float bx = qx / scl;
        float by = qy / scl;
        int ix = (int)floorf(bx);
        int iy = (int)floorf(by);

        // ---- D table: 64 window dots, 8 positions per warp ----
        const float* fb = f2n + (size_t)b * Hl * Wl * NC;
        const float4* f1p = (const float4*)feat1;
        float4 q0 = f1p[lane];
        float4 q1 = f1p[lane + 32];
#pragma unroll
        for (int pp = 0; pp < 8; pp++) {
            int p = wid * 8 + pp;       // warp `wid` owns window row `wid`
            int wi = p >> 3, wj = p & 7;
            int yy = min(max(iy - 3 + wi, 0), Hl - 1);
            int xx = min(max(ix - 3 + wj, 0), Wl - 1);
            const float4* rowp = (const float4*)(fb + ((size_t)yy * Wl + xx) * NC);
            float4 a0 = rowp[lane];
            float4 a1 = rowp[lane + 32];
            float acc = a0.x * q0.x + a0.y * q0.y + a0.z * q0.z + a0.w * q0.w +
                        a1.x * q1.x + a1.y * q1.y + a1.z * q1.z + a1.w * q1.w;
#pragma unroll
            for (int o = 16; o > 0; o >>= 1) acc += __shfl_xor_sync(0xffffffffu, acc, o);
            if (lane == 0) D[p] = acc;
        }
        __syncthreads();

        // ---- 49 outputs: scalar bilinear blend of D ----
        if (tid < NK) {
            int dy = tid / 7 - 3;   // offs is dy-major (meshgrid 'ij', raveled)
            int dx = tid % 7 - 3;
            float xk = fminf(fmaxf(bx + (float)dx, 0.0f), (float)(Wl - 1));
            float yk = fminf(fmaxf(by + (float)dy, 0.0f), (float)(Hl - 1));
            float fx = floorf(xk), fy = floorf(yk);
            float xh = fminf(fx + 1.0f, (float)(Wl - 1));
            float yh = fminf(fy + 1.0f, (float)(Hl - 1));
            // Weights from CLIPPED corner indices (reproduces the border-zero quirk).
            float wx1 = xk - fx, wx0 = xh - xk;
            float wy1 = yk - fy, wy0 = yh - yk;
            int jx0 = dx + 3, jx1 = dx + 4;
            int jy0 = dy + 3, jy1 = dy + 4;
            float val = wx0 * wy0 * D[jy0 * 8 + jx0] + wx0 * wy1 * D[jy1 * 8 + jx0] +
                        wx1 * wy0 * D[jy0 * 8 + jx1] + wx1 * wy1 * D[jy1 * 8 + jx1];
            out[((size_t)b * NQ + n) * (NLEV * NK) + l * NK + tid] = val;
        }
        __syncthreads();  // protect D before next level overwrites it
    }
}

extern "C" void kernel_launch(void* const* d_in, const int* in_sizes, int n_in,
                              void* d_out, int out_size) {
    const float* fmap1   = (const float*)d_in[0];
    const float* fmap2   = (const float*)d_in[1];
    const float* coords1 = (const float*)d_in[2];
    const float* coords2 = (const float*)d_in[3];
    float* out = (float*)d_out;

    float *pyr1, *pyr2, *pyr3, *f2n0, *f2n1, *f2n2, *f2n3;
    cudaGetSymbolAddress((void**)&pyr1, g_pyr1);
    cudaGetSymbolAddress((void**)&pyr2, g_pyr2);
    cudaGetSymbolAddress((void**)&pyr3, g_pyr3);
    cudaGetSymbolAddress((void**)&f2n0, g_f2n0);
    cudaGetSymbolAddress((void**)&f2n1, g_f2n1);
    cudaGetSymbolAddress((void**)&f2n2, g_f2n2);
    cudaGetSymbolAddress((void**)&f2n3, g_f2n3);

    // Cascaded pyramid (un-normalized), matching jax.image.resize antialiased bilinear.
    downsample_kernel<<<dim3(32 * 32, NB), 256>>>(fmap2, pyr1, 64, 64);
    downsample_kernel<<<dim3(16 * 16, NB), 256>>>(pyr1, pyr2, 32, 32);
    downsample_kernel<<<dim3(8 * 8, NB), 256>>>(pyr2, pyr3, 16, 16);

    // Per-level L2 normalization.
    normalize_kernel<<<dim3(64 * 64, NB), 256>>>(fmap2, f2n0, 64 * 64);
    normalize_kernel<<<dim3(32 * 32, NB), 256>>>(pyr1, f2n1, 32 * 32);
    normalize_kernel<<<dim3(16 * 16, NB), 256>>>(pyr2, f2n2, 16 * 16);
    normalize_kernel<<<dim3(8 * 8, NB), 256>>>(pyr3, f2n3, 8 * 8);

    // Main correlation kernel: one block per (b, n).
    corr_kernel<<<dim3(NQ, NB), 256>>>(fmap1, coords1, coords2,
                                       f2n0, f2n1, f2n2, f2n3, out);
}